// round 5
// baseline (speedup 1.0000x reference)
#include <cuda_runtime.h>

#define BATCH 32
#define NIN   2312
#define NHID  512
#define NOUT  10
#define TT    350
#define TKLEN 100
#define NIG   73    // ceil(NIN/32) mask words per (b,t)
#define NHG   (NHID/32)

#define THETA 10.0f
#define D_SR  0.90483741803595952f     // exp(-0.1)
#define C_SR  0.27182818284590452f     // e/10
#define E10   4.5399929762484854e-05f  // exp(-10)
#define D_REF 0.36787944117144233f     // exp(-1)
#define C_REF -54.365636569180902f     // -20e

#define SCTC  28    // scan1 chunk length (ring slot distance check: 100 < 128-SCTC+... safe)

// scratch (allocation-free: device globals)
__device__ float    g_W1T[(size_t)NIN * NHID];          // [i][h]
__device__ unsigned g_M  [(size_t)BATCH * TT * NIG];    // X bitmasks [b][t][ig]
__device__ float    g_G1 [(size_t)BATCH * TT * NHID];   // [b][t][h]
__device__ unsigned g_S1b[(size_t)BATCH * TT * NHG];    // s1 bitmasks [b][t][hg]
__device__ float    g_G2 [(size_t)BATCH * TT * NOUT];   // [b][t][o]

// ---------------------------------------------------------------------------
// Transpose W1 [NHID][NIN] -> W1T [NIN][NHID]
// ---------------------------------------------------------------------------
__global__ void __launch_bounds__(256) w1t_kernel(const float* __restrict__ W1) {
    __shared__ float tile[32][33];
    int i0 = blockIdx.x * 32;
    int h0 = blockIdx.y * 32;
    int lx = threadIdx.x & 31;
    int ly = threadIdx.x >> 5;

    #pragma unroll
    for (int r = 0; r < 4; r++) {
        int h = h0 + ly + r * 8;
        int i = i0 + lx;
        tile[ly + r * 8][lx] = (i < NIN) ? W1[(size_t)h * NIN + i] : 0.f;
    }
    __syncthreads();
    #pragma unroll
    for (int r = 0; r < 4; r++) {
        int i = i0 + ly + r * 8;
        int h = h0 + lx;
        if (i < NIN) g_W1T[(size_t)i * NHID + h] = tile[lx][ly + r * 8];
    }
}

// ---------------------------------------------------------------------------
// Mask build: block per (b, ig). Stage 32 rows of X coalescedly in smem,
// then thread t packs the 32-bit word -> g_M[b][t][ig].
// ---------------------------------------------------------------------------
__global__ void __launch_bounds__(352) maskbuild_kernel(const float* __restrict__ X) {
    __shared__ float xs[32][TT];
    const int ig = blockIdx.x;
    const int b  = blockIdx.y;
    const int tid = threadIdx.x;

    #pragma unroll 1
    for (int j = 0; j < 32; j++) {
        int i = ig * 32 + j;
        if (tid < TT)
            xs[j][tid] = (i < NIN) ? X[((size_t)b * NIN + i) * TT + tid] : 0.f;
    }
    __syncthreads();

    if (tid < TT) {
        unsigned w = 0;
        #pragma unroll
        for (int j = 0; j < 32; j++)
            if (xs[j][tid] != 0.f) w |= 1u << j;
        g_M[((size_t)b * TT + tid) * NIG + ig] = w;
    }
}

// ---------------------------------------------------------------------------
// Sparse GEMM1: warp per (b,t); 8 consecutive t per block (L1 row reuse).
// Gathers active W1T rows in ascending-i order (deterministic).
// ---------------------------------------------------------------------------
__device__ __forceinline__ void add4(float4& a, const float4& r) {
    a.x += r.x; a.y += r.y; a.z += r.z; a.w += r.w;
}

__global__ void __launch_bounds__(256) spgemm1_kernel() {
    const int warp = threadIdx.x >> 5;
    const int lane = threadIdx.x & 31;
    const int b = blockIdx.y;
    const int t = blockIdx.x * 8 + warp;
    if (t >= TT) return;

    const unsigned* __restrict__ mrow = g_M + ((size_t)b * TT + t) * NIG;

    float4 acc0 = make_float4(0.f, 0.f, 0.f, 0.f);
    float4 acc1 = acc0, acc2 = acc0, acc3 = acc0;

    #pragma unroll
    for (int cb = 0; cb < 96; cb += 32) {
        unsigned mw = (cb + lane < NIG) ? mrow[cb + lane] : 0u;
        unsigned act = __ballot_sync(0xffffffffu, mw != 0u);
        while (act) {
            int j = __ffs(act) - 1;
            act &= act - 1;
            unsigned w = __shfl_sync(0xffffffffu, mw, j);
            int ibase = (cb + j) * 32;
            while (w) {
                int bit = __ffs(w) - 1;
                w &= w - 1;
                const float4* row = (const float4*)(g_W1T + (size_t)(ibase + bit) * NHID);
                float4 r0 = row[lane];
                float4 r1 = row[lane + 32];
                float4 r2 = row[lane + 64];
                float4 r3 = row[lane + 96];
                add4(acc0, r0); add4(acc1, r1); add4(acc2, r2); add4(acc3, r3);
            }
        }
    }

    float4* out = (float4*)(g_G1 + ((size_t)b * TT + t) * NHID);
    out[lane]      = acc0;
    out[lane + 32] = acc1;
    out[lane + 64] = acc2;
    out[lane + 96] = acc3;
}

// ---------------------------------------------------------------------------
// scan1: block = (b, 64-h slice), 64 threads, one channel each.
// G1 staged in 28-t chunks into a 128-slot smem ring; the t-100 refractory
// tail read comes from the ring (distance 100..128 always resident).
// Emits spike bitmasks via ballot. Arithmetic identical to prior rounds.
// ---------------------------------------------------------------------------
__global__ void __launch_bounds__(64) scan1_kernel() {
    __shared__ float ring[128][64];   // 32 KB

    const int b   = blockIdx.y;
    const int h0  = blockIdx.x * 64;
    const int tid = threadIdx.x;
    const int lane = tid & 31;
    const int hg  = (h0 + tid) >> 5;   // = blockIdx.x*2 + warp

    const float* __restrict__ g = g_G1 + (size_t)b * TT * NHID + h0 + tid;
    unsigned* __restrict__ sb = g_S1b + (size_t)b * TT * NHG + hg;

    float pa = 0.f, pb = 0.f;
    float qa = 0.f, qb = 0.f;
    float ra = 0.f, rb = 0.f;

    for (int t0 = 0; t0 < TT; t0 += SCTC) {
        const int tc = (TT - t0 < SCTC) ? (TT - t0) : SCTC;

        // stage chunk [t0, t0+tc) into ring (coalesced, high MLP)
        #pragma unroll
        for (int tt = 0; tt < SCTC; tt++) {
            if (tt < tc)
                ring[(t0 + tt) & 127][tid] = __ldg(&g[(size_t)(t0 + tt) * NHID]);
        }
        __syncthreads();

        #pragma unroll
        for (int tt = 0; tt < SCTC; tt++) {
            if (tt >= tc) break;
            int t = t0 + tt;
            float gv = ring[t & 127][tid];
            float gd = (t >= TKLEN) ? ring[(t - TKLEN) & 127][tid] : 0.f;

            float pa_o = pa, qa_o = qa, ra_o = ra;
            pa = fmaf(D_SR, pa_o, gv);
            pb = fmaf(D_SR, pb, D_SR * pa_o);
            qa = fmaf(D_SR, qa_o, gd);
            qb = fmaf(D_SR, qb, D_SR * qa_o);

            float y = C_SR * (pb - E10 * fmaf(100.f, qa, qb));
            float u = fmaf(C_REF, rb, y);
            float sp = (u >= THETA) ? 1.f : 0.f;

            ra = fmaf(D_REF, ra_o, sp);
            rb = fmaf(D_REF, rb, D_REF * ra_o);

            unsigned wbits = __ballot_sync(0xffffffffu, sp != 0.f);
            if (lane == 0) sb[(size_t)t * NHG] = wbits;
        }
        __syncthreads();
    }
}

// ---------------------------------------------------------------------------
// GEMM2 (sparse): warp per (b,t). Spikes are exactly 1.0 -> G2[t][o] is a sum
// of W2^T rows over active h (ascending order). Lanes 0..9 hold outputs.
// ---------------------------------------------------------------------------
__global__ void __launch_bounds__(256) gemm2_kernel(const float* __restrict__ W2) {
    __shared__ float w2t[NHID * NOUT];   // transposed [h][o], 20 KB
    for (int i = threadIdx.x; i < NOUT * NHID; i += 256) {
        int o = i / NHID, h = i - o * NHID;
        w2t[h * NOUT + o] = W2[i];
    }
    __syncthreads();

    const int b = blockIdx.y;
    const int t = blockIdx.x * 8 + (threadIdx.x >> 5);
    const int lane = threadIdx.x & 31;
    if (t >= TT) return;

    const unsigned* srow = g_S1b + ((size_t)b * TT + t) * NHG;
    unsigned mw = (lane < NHG) ? srow[lane] : 0u;

    float acc = 0.f;   // lane<10: accumulator for o=lane
    unsigned act = __ballot_sync(0xffffffffu, mw != 0u);
    while (act) {
        int j = __ffs(act) - 1;
        act &= act - 1;
        unsigned w = __shfl_sync(0xffffffffu, mw, j);
        int hbase = j * 32;
        while (w) {
            int bit = __ffs(w) - 1;
            w &= w - 1;
            if (lane < NOUT) acc += w2t[(hbase + bit) * NOUT + lane];
        }
    }
    if (lane < NOUT)
        g_G2[((size_t)b * TT + t) * NOUT + lane] = acc;
}

// ---------------------------------------------------------------------------
// scan2: block per b. Stage G2[b] into smem, 10 threads run the spike scan.
// ---------------------------------------------------------------------------
__global__ void __launch_bounds__(128) scan2_kernel(float* __restrict__ out) {
    __shared__ float g2s[TT * NOUT];
    const int b = blockIdx.x;

    const float* src = g_G2 + (size_t)b * TT * NOUT;
    for (int i = threadIdx.x; i < TT * NOUT; i += 128) g2s[i] = src[i];
    __syncthreads();

    if (threadIdx.x < NOUT) {
        const int o = threadIdx.x;
        float* y_out = out + ((size_t)b * NOUT + o) * TT;

        float pa = 0.f, pb = 0.f, qa = 0.f, qb = 0.f, ra = 0.f, rb = 0.f;
        for (int t = 0; t < TT; t++) {
            float gv = g2s[t * NOUT + o];
            float gd = (t >= TKLEN) ? g2s[(t - TKLEN) * NOUT + o] : 0.f;

            float pa_o = pa, qa_o = qa, ra_o = ra;
            pa = fmaf(D_SR, pa_o, gv);
            pb = fmaf(D_SR, pb, D_SR * pa_o);
            qa = fmaf(D_SR, qa_o, gd);
            qb = fmaf(D_SR, qb, D_SR * qa_o);

            float y = C_SR * (pb - E10 * fmaf(100.f, qa, qb));
            float u = fmaf(C_REF, rb, y);
            float sp = (u >= THETA) ? 1.f : 0.f;

            ra = fmaf(D_REF, ra_o, sp);
            rb = fmaf(D_REF, rb, D_REF * ra_o);

            y_out[t] = sp;
        }
    }
}

// ---------------------------------------------------------------------------
extern "C" void kernel_launch(void* const* d_in, const int* in_sizes, int n_in,
                              void* d_out, int out_size) {
    const float* X  = (const float*)d_in[0];   // [32][2312][350]
    const float* W1 = (const float*)d_in[1];   // [512][2312]
    const float* W2 = (const float*)d_in[2];   // [10][512]
    float* out = (float*)d_out;                // [32][10][350]

    dim3 gT((NIN + 31) / 32, NHID / 32);
    w1t_kernel<<<gT, 256>>>(W1);

    dim3 gM(NIG, BATCH);
    maskbuild_kernel<<<gM, 352>>>(X);

    dim3 gS((TT + 7) / 8, BATCH);
    spgemm1_kernel<<<gS, 256>>>();

    dim3 gScan(NHID / 64, BATCH);   // (8, 32) = 256 blocks
    scan1_kernel<<<gScan, 64>>>();

    dim3 gG2((TT + 7) / 8, BATCH);
    gemm2_kernel<<<gG2, 256>>>(W2);

    scan2_kernel<<<BATCH, 128>>>(out);
}